// round 6
// baseline (speedup 1.0000x reference)
#include <cuda_runtime.h>

#define NB 2
#define NC 64
#define D  64
#define NVOX (D*D*D)            // 262144
#define NCH  (NB*NC)            // 128
#define TOT  (NCH*NVOX)         // 33554432

#define FIX_T   0.02f
#define MAXFIX  (1<<22)

#define PSTR 65                 // padded smem row stride (float2 elems)

// Scratch (no cudaMalloc allowed)
__device__ float2 g_p [TOT];    // (qk, qkv) bit-exact proj output (fixup source)
__device__ float2 g_t2[TOT];    // after w+h passes
__device__ int    g_cnt;
__device__ int    g_fixlist[MAXFIX];

__global__ void reset_kernel() { g_cnt = 0; }

// ---------------------------------------------------------------------------
// Stage 1: per-voxel projections. Two packed fma.rn.f32x2 streams:
//   stream A: lanes (aq, ak), weights (wq,wk), operand (m,f)
//   stream B: lanes (0,  av), weights (0, wv), operand (m,f)
// Each lane is an IEEE fp32 FMA -> bit-identical to scalar sequential
// ascending-c chains (load-bearing for near-zero denominators; see fixup).
// Live state = mf[64] (128 regs). __launch_bounds__(256,1) -> no reg cap,
// no spill. No block barriers in the main loop.
// ---------------------------------------------------------------------------
__global__ __launch_bounds__(256, 1) void proj_kernel(
    const float* __restrict__ mov, const float* __restrict__ fix,
    const float* __restrict__ qw,  const float* __restrict__ kw,
    const float* __restrict__ vw)
{
    extern __shared__ float2 sm2[];
    float2* swqk = sm2;            // [NC*NC] (wq,wk)  32 KB
    float2* swv2 = sm2 + NC*NC;    // [NC*NC] (0, wv)  32 KB

    const int tid = threadIdx.x;
    for (int i = tid; i < NC*NC; i += 256) {
        swqk[i] = make_float2(qw[i], kw[i]);
        swv2[i] = make_float2(0.f, vw[i]);
    }
    __syncthreads();

    const int gid = blockIdx.x * 256 + tid;     // 0 .. NB*NVOX-1
    const int b   = (gid >= NVOX) ? 1 : 0;
    const int n   = gid - b * NVOX;

    const float* mp = mov + (long)b*NC*NVOX + n;
    const float* fp = fix + (long)b*NC*NVOX + n;

    unsigned long long mf[NC];   // packed (m[c], f[c])
    #pragma unroll
    for (int c = 0; c < NC; c++) {
        const float mv = mp[(long)c*NVOX];
        const float fv = fp[(long)c*NVOX];
        asm("mov.b64 %0, {%1,%2};" : "=l"(mf[c]) : "f"(mv), "f"(fv));
    }

    float2* op = g_p + (long)b*NC*NVOX + n;

    #pragma unroll 1
    for (int l = 0; l < NC; l++) {
        const ulonglong2* wrow = (const ulonglong2*)(swqk + (l<<6));
        const ulonglong2* vrow = (const ulonglong2*)(swv2 + (l<<6));
        unsigned long long aqk = 0ull;   // lanes (aq, ak)
        unsigned long long avv = 0ull;   // lanes (0,  av)
        #pragma unroll
        for (int j = 0; j < NC/4; j++) {
            const ulonglong2 wa = wrow[2*j];
            const ulonglong2 wb = wrow[2*j+1];
            const ulonglong2 va = vrow[2*j];
            const ulonglong2 vb = vrow[2*j+1];
            asm("fma.rn.f32x2 %0, %1, %2, %0;" : "+l"(aqk) : "l"(wa.x), "l"(mf[4*j+0]));
            asm("fma.rn.f32x2 %0, %1, %2, %0;" : "+l"(avv) : "l"(va.x), "l"(mf[4*j+0]));
            asm("fma.rn.f32x2 %0, %1, %2, %0;" : "+l"(aqk) : "l"(wa.y), "l"(mf[4*j+1]));
            asm("fma.rn.f32x2 %0, %1, %2, %0;" : "+l"(avv) : "l"(va.y), "l"(mf[4*j+1]));
            asm("fma.rn.f32x2 %0, %1, %2, %0;" : "+l"(aqk) : "l"(wb.x), "l"(mf[4*j+2]));
            asm("fma.rn.f32x2 %0, %1, %2, %0;" : "+l"(avv) : "l"(vb.x), "l"(mf[4*j+2]));
            asm("fma.rn.f32x2 %0, %1, %2, %0;" : "+l"(aqk) : "l"(wb.y), "l"(mf[4*j+3]));
            asm("fma.rn.f32x2 %0, %1, %2, %0;" : "+l"(avv) : "l"(vb.y), "l"(mf[4*j+3]));
        }
        float aq, ak, zz, av;
        asm("mov.b64 {%0,%1}, %2;" : "=f"(aq), "=f"(ak) : "l"(aqk));
        asm("mov.b64 {%0,%1}, %2;" : "=f"(zz), "=f"(av) : "l"(avv));
        const float qk  = __fmul_rn(aq, ak);
        const float qkv = __fmul_rn(qk, av);
        op[(long)l*NVOX] = make_float2(qk, qkv);
    }
}

// ---------------------------------------------------------------------------
// Stage 2ab (fused): box sums along W then H for one (chan, z) plane.
// Plane (64h x 64w) of float2 staged in smem (padded stride 65), w-pass ring
// per 16-wide segment, then h-pass ring, write g_t2.  g_p -> g_t2
// ---------------------------------------------------------------------------
__global__ __launch_bounds__(256) void box_wh_kernel()
{
    extern __shared__ float2 smp[];
    float2* P = smp;               // [64][PSTR] input plane
    float2* Q = smp + D*PSTR;      // [64][PSTR] after w-pass

    const int tid  = threadIdx.x;
    const int z    = blockIdx.x;
    const int chan = blockIdx.y;
    const long base = (long)chan*NVOX + (long)z*(D*D);

    // load plane (coalesced float2)
    for (int i = tid; i < D*D; i += 256) {
        const int h = i >> 6, w = i & 63;
        P[h*PSTR + w] = g_p[base + i];
    }
    __syncthreads();

    // w-pass: thread = (h = tid&63, seg = tid>>6), 16 outputs per thread
    {
        const int h   = tid & 63;
        const int seg = tid >> 6;
        const int w0  = seg * 16;
        const float2* row = P + h*PSTR;
        float2* qrow = Q + h*PSTR;
        float2 ring[9];
        float sx = 0.f, sy = 0.f;
        #pragma unroll
        for (int j = w0-4; j < w0+4; j++) {
            if (j >= 0) {
                float2 v = row[j];
                ring[(j+36)%9] = v; sx += v.x; sy += v.y;
            }
        }
        #pragma unroll
        for (int i = 0; i < 16; i++) {
            const int w = w0 + i;
            const int j = w + 4;
            if (j < D) {
                float2 v = row[j];
                ring[(j+36)%9] = v; sx += v.x; sy += v.y;
            }
            qrow[w] = make_float2(sx, sy);
            const int j2 = w - 4;
            if (j2 >= 0) { sx -= ring[(j2+36)%9].x; sy -= ring[(j2+36)%9].y; }
        }
    }
    __syncthreads();

    // h-pass: thread = (w = tid&63, seg = tid>>6), ring over h, write g_t2
    {
        const int w   = tid & 63;
        const int seg = tid >> 6;
        const int h0  = seg * 16;
        float2 ring[9];
        float sx = 0.f, sy = 0.f;
        #pragma unroll
        for (int j = h0-4; j < h0+4; j++) {
            if (j >= 0) {
                float2 v = Q[j*PSTR + w];
                ring[(j+36)%9] = v; sx += v.x; sy += v.y;
            }
        }
        #pragma unroll
        for (int i = 0; i < 16; i++) {
            const int h = h0 + i;
            const int j = h + 4;
            if (j < D) {
                float2 v = Q[j*PSTR + w];
                ring[(j+36)%9] = v; sx += v.x; sy += v.y;
            }
            g_t2[base + h*D + w] = make_float2(sx, sy);
            const int j2 = h - 4;
            if (j2 >= 0) { sx -= ring[(j2+36)%9].x; sy -= ring[(j2+36)%9].y; }
        }
    }
}

// ---------------------------------------------------------------------------
// Stage 2c: box sum along Z + division; flag near-zero denominators.
// g_t2 -> out
// ---------------------------------------------------------------------------
__global__ __launch_bounds__(256) void box_z_div_kernel(float* __restrict__ out)
{
    const int t    = threadIdx.x;
    const int wp   = t & 31;
    const int h    = blockIdx.x * 8 + (t >> 5);   // gridDim.x = 8
    const int chan = blockIdx.y;
    const long ebase = (long)chan*NVOX + (long)h*D + 2*wp;
    const long base  = ebase >> 1;
    const float4* src = (const float4*)g_t2;
    float2*       o2  = (float2*)out;

    float4 ring[9];
    float4 s = make_float4(0.f, 0.f, 0.f, 0.f);
    #pragma unroll
    for (int j = 0; j < 4; j++) {
        float4 v = src[base + (long)j*(D*D/2)];
        ring[j % 9] = v;
        s.x += v.x; s.y += v.y; s.z += v.z; s.w += v.w;
    }
    #pragma unroll
    for (int i = 0; i < D; i++) {
        const int j = i + 4;
        if (j < D) {
            float4 v = src[base + (long)j*(D*D/2)];
            ring[j % 9] = v;
            s.x += v.x; s.y += v.y; s.z += v.z; s.w += v.w;
        }
        const long eidx = ebase + (long)i*(D*D);
        o2[eidx >> 1] = make_float2(__fdiv_rn(s.y, s.x), __fdiv_rn(s.w, s.z));
        if (fabsf(s.x) < FIX_T) {
            int slot = atomicAdd(&g_cnt, 1);
            if (slot < MAXFIX) g_fixlist[slot] = (int)eidx;
        }
        if (fabsf(s.z) < FIX_T) {
            int slot = atomicAdd(&g_cnt, 1);
            if (slot < MAXFIX) g_fixlist[slot] = (int)(eidx + 1);
        }
        const int j2 = i - 4;
        if (j2 >= 0) {
            float4 v = ring[j2 % 9];
            s.x -= v.x; s.y -= v.y; s.z -= v.z; s.w -= v.w;
        }
    }
}

// ---------------------------------------------------------------------------
// Stage 3: exact fixup — reference's sequential in-bounds 729-tap fold
// (ascending z,h,w; fp32 adds; init 0) over the bit-exact g_p field.
// ---------------------------------------------------------------------------
__global__ __launch_bounds__(256) void fixup_kernel(float* __restrict__ out)
{
    int cnt = g_cnt; if (cnt > MAXFIX) cnt = MAXFIX;
    for (int idx = blockIdx.x*256 + threadIdx.x; idx < cnt; idx += gridDim.x*256) {
        const int v    = g_fixlist[idx];
        const int chan = v >> 18;
        const int rem  = v & (NVOX-1);
        const int z = rem >> 12;
        const int h = (rem >> 6) & 63;
        const int w = rem & 63;
        const long cb = (long)chan*NVOX;

        const int zlo = z-4 < 0 ? 0 : z-4, zhi = z+4 > 63 ? 63 : z+4;
        const int hlo = h-4 < 0 ? 0 : h-4, hhi = h+4 > 63 ? 63 : h+4;
        const int wlo = w-4 < 0 ? 0 : w-4, whi = w+4 > 63 ? 63 : w+4;

        float sD = 0.f, sN = 0.f;
        for (int dz = zlo; dz <= zhi; dz++)
            for (int dh = hlo; dh <= hhi; dh++) {
                const float2* row = g_p + cb + ((long)dz*D + dh)*D;
                for (int dw = wlo; dw <= whi; dw++) {
                    float2 x = row[dw];
                    sD = __fadd_rn(sD, x.x);
                    sN = __fadd_rn(sN, x.y);
                }
            }
        out[v] = __fdiv_rn(sN, sD);
    }
}

extern "C" void kernel_launch(void* const* d_in, const int* in_sizes, int n_in,
                              void* d_out, int out_size) {
    (void)in_sizes; (void)n_in; (void)out_size;
    const float* mov = (const float*)d_in[0];
    const float* fix = (const float*)d_in[1];
    const float* qw  = (const float*)d_in[2];
    const float* kw  = (const float*)d_in[3];
    const float* vw  = (const float*)d_in[4];
    float* out = (float*)d_out;

    const int proj_smem = 2*NC*NC * sizeof(float2);       // 65536 B
    const int wh_smem   = 2*D*PSTR * sizeof(float2);      // 66560 B
    cudaFuncSetAttribute(proj_kernel,
                         cudaFuncAttributeMaxDynamicSharedMemorySize, proj_smem);
    cudaFuncSetAttribute(box_wh_kernel,
                         cudaFuncAttributeMaxDynamicSharedMemorySize, wh_smem);

    reset_kernel<<<1, 1>>>();
    proj_kernel<<<(NB*NVOX)/256, 256, proj_smem>>>(mov, fix, qw, kw, vw);
    box_wh_kernel<<<dim3(D, NCH), 256, wh_smem>>>();
    box_z_div_kernel<<<dim3(8, NCH), 256>>>(out);
    fixup_kernel<<<512, 256>>>(out);
}

// round 7
// speedup vs baseline: 1.1111x; 1.1111x over previous
#include <cuda_runtime.h>

#define NB 2
#define NC 64
#define D  64
#define NVOX (D*D*D)            // 262144
#define NCH  (NB*NC)            // 128
#define TOT  (NCH*NVOX)         // 33554432

#define FIX_T   0.02f
#define MAXFIX  (1<<22)

#define PSTR 65                 // padded smem row stride (float2 elems)

// Scratch (no cudaMalloc allowed)
__device__ float2 g_p [TOT];    // (qk, qkv) bit-exact proj output (fixup source)
__device__ float2 g_t2[TOT];    // after w+h passes
__device__ int    g_cnt;
__device__ int    g_fixlist[MAXFIX];

__global__ void reset_kernel() { g_cnt = 0; }

// ---------------------------------------------------------------------------
// Stage 1: per-voxel projections (R4-proven version, byte-identical).
// aq/ak as one packed fma.rn.f32x2 chain (each lane IEEE fp32 -> bit-identical
// to scalar sequential ascending-c chains); av as scalar FFMA chain.
// qk = q*k; qkv = qk*v single roundings. Bit-exactness of g_p is load-bearing
// for near-zero-denominator voxels (see fixup).
// ---------------------------------------------------------------------------
__global__ __launch_bounds__(256) void proj_kernel(
    const float* __restrict__ mov, const float* __restrict__ fix,
    const float* __restrict__ qw,  const float* __restrict__ kw,
    const float* __restrict__ vw)
{
    __shared__ float2 swqk[NC*NC];   // (wq, wk) interleaved, 32 KB
    __shared__ float  swv [NC*NC];   // 16 KB
    const int tid = threadIdx.x;
    for (int i = tid; i < NC*NC; i += 256) {
        swqk[i] = make_float2(qw[i], kw[i]);
        swv[i]  = vw[i];
    }
    __syncthreads();

    const int gid = blockIdx.x * 256 + tid;     // 0 .. NB*NVOX-1
    const int b   = (gid >= NVOX) ? 1 : 0;
    const int n   = gid - b * NVOX;

    const float* mp = mov + (long)b*NC*NVOX + n;
    const float* fp = fix + (long)b*NC*NVOX + n;

    unsigned long long mf[NC];   // packed (m[c], f[c])
    float f[NC];
    #pragma unroll
    for (int c = 0; c < NC; c++) {
        const float mv = mp[(long)c*NVOX];
        const float fv = fp[(long)c*NVOX];
        f[c] = fv;
        asm("mov.b64 %0, {%1,%2};" : "=l"(mf[c]) : "f"(mv), "f"(fv));
    }

    float2* op = g_p + (long)b*NC*NVOX + n;

    for (int l = 0; l < NC; l++) {
        const ulonglong2* wrow = (const ulonglong2*)(swqk + (l<<6));
        const float4*     vrow = (const float4*)(swv + (l<<6));
        unsigned long long aqk = 0ull;   // lanes: (aq, ak)
        float av = 0.f;
        #pragma unroll
        for (int j = 0; j < NC/4; j++) {
            const ulonglong2 wa = wrow[2*j];      // c = 4j, 4j+1
            const ulonglong2 wb = wrow[2*j+1];    // c = 4j+2, 4j+3
            const float4 wv4 = vrow[j];
            asm("fma.rn.f32x2 %0, %1, %2, %0;" : "+l"(aqk) : "l"(wa.x), "l"(mf[4*j+0]));
            av = __fmaf_rn(wv4.x, f[4*j+0], av);
            asm("fma.rn.f32x2 %0, %1, %2, %0;" : "+l"(aqk) : "l"(wa.y), "l"(mf[4*j+1]));
            av = __fmaf_rn(wv4.y, f[4*j+1], av);
            asm("fma.rn.f32x2 %0, %1, %2, %0;" : "+l"(aqk) : "l"(wb.x), "l"(mf[4*j+2]));
            av = __fmaf_rn(wv4.z, f[4*j+2], av);
            asm("fma.rn.f32x2 %0, %1, %2, %0;" : "+l"(aqk) : "l"(wb.y), "l"(mf[4*j+3]));
            av = __fmaf_rn(wv4.w, f[4*j+3], av);
        }
        float aq, ak;
        asm("mov.b64 {%0,%1}, %2;" : "=f"(aq), "=f"(ak) : "l"(aqk));
        const float qk  = __fmul_rn(aq, ak);
        const float qkv = __fmul_rn(qk, av);
        op[(long)l*NVOX] = make_float2(qk, qkv);
    }
}

// ---------------------------------------------------------------------------
// Stage 2ab (fused): box sums along W then H for one (chan, z) plane.
// Plane (64h x 64w) of float2 staged in smem (padded stride 65), w-pass ring
// per 16-wide segment, then h-pass ring, write g_t2.  g_p -> g_t2
// ---------------------------------------------------------------------------
__global__ __launch_bounds__(256) void box_wh_kernel()
{
    extern __shared__ float2 smp[];
    float2* P = smp;               // [64][PSTR] input plane
    float2* Q = smp + D*PSTR;      // [64][PSTR] after w-pass

    const int tid  = threadIdx.x;
    const int z    = blockIdx.x;
    const int chan = blockIdx.y;
    const long base = (long)chan*NVOX + (long)z*(D*D);

    // load plane (coalesced float2)
    for (int i = tid; i < D*D; i += 256) {
        const int h = i >> 6, w = i & 63;
        P[h*PSTR + w] = g_p[base + i];
    }
    __syncthreads();

    // w-pass: thread = (h = tid&63, seg = tid>>6), 16 outputs per thread
    {
        const int h   = tid & 63;
        const int seg = tid >> 6;
        const int w0  = seg * 16;
        const float2* row = P + h*PSTR;
        float2* qrow = Q + h*PSTR;
        float2 ring[9];
        float sx = 0.f, sy = 0.f;
        #pragma unroll
        for (int j = w0-4; j < w0+4; j++) {
            if (j >= 0) {
                float2 v = row[j];
                ring[(j+36)%9] = v; sx += v.x; sy += v.y;
            }
        }
        #pragma unroll
        for (int i = 0; i < 16; i++) {
            const int w = w0 + i;
            const int j = w + 4;
            if (j < D) {
                float2 v = row[j];
                ring[(j+36)%9] = v; sx += v.x; sy += v.y;
            }
            qrow[w] = make_float2(sx, sy);
            const int j2 = w - 4;
            if (j2 >= 0) { sx -= ring[(j2+36)%9].x; sy -= ring[(j2+36)%9].y; }
        }
    }
    __syncthreads();

    // h-pass: thread = (w = tid&63, seg = tid>>6), ring over h, write g_t2
    {
        const int w   = tid & 63;
        const int seg = tid >> 6;
        const int h0  = seg * 16;
        float2 ring[9];
        float sx = 0.f, sy = 0.f;
        #pragma unroll
        for (int j = h0-4; j < h0+4; j++) {
            if (j >= 0) {
                float2 v = Q[j*PSTR + w];
                ring[(j+36)%9] = v; sx += v.x; sy += v.y;
            }
        }
        #pragma unroll
        for (int i = 0; i < 16; i++) {
            const int h = h0 + i;
            const int j = h + 4;
            if (j < D) {
                float2 v = Q[j*PSTR + w];
                ring[(j+36)%9] = v; sx += v.x; sy += v.y;
            }
            g_t2[base + h*D + w] = make_float2(sx, sy);
            const int j2 = h - 4;
            if (j2 >= 0) { sx -= ring[(j2+36)%9].x; sy -= ring[(j2+36)%9].y; }
        }
    }
}

// ---------------------------------------------------------------------------
// Stage 2c: box sum along Z + division; flag near-zero denominators.
// g_t2 -> out
// ---------------------------------------------------------------------------
__global__ __launch_bounds__(256) void box_z_div_kernel(float* __restrict__ out)
{
    const int t    = threadIdx.x;
    const int wp   = t & 31;
    const int h    = blockIdx.x * 8 + (t >> 5);   // gridDim.x = 8
    const int chan = blockIdx.y;
    const long ebase = (long)chan*NVOX + (long)h*D + 2*wp;
    const long base  = ebase >> 1;
    const float4* src = (const float4*)g_t2;
    float2*       o2  = (float2*)out;

    float4 ring[9];
    float4 s = make_float4(0.f, 0.f, 0.f, 0.f);
    #pragma unroll
    for (int j = 0; j < 4; j++) {
        float4 v = src[base + (long)j*(D*D/2)];
        ring[j % 9] = v;
        s.x += v.x; s.y += v.y; s.z += v.z; s.w += v.w;
    }
    #pragma unroll
    for (int i = 0; i < D; i++) {
        const int j = i + 4;
        if (j < D) {
            float4 v = src[base + (long)j*(D*D/2)];
            ring[j % 9] = v;
            s.x += v.x; s.y += v.y; s.z += v.z; s.w += v.w;
        }
        const long eidx = ebase + (long)i*(D*D);
        o2[eidx >> 1] = make_float2(__fdiv_rn(s.y, s.x), __fdiv_rn(s.w, s.z));
        if (fabsf(s.x) < FIX_T) {
            int slot = atomicAdd(&g_cnt, 1);
            if (slot < MAXFIX) g_fixlist[slot] = (int)eidx;
        }
        if (fabsf(s.z) < FIX_T) {
            int slot = atomicAdd(&g_cnt, 1);
            if (slot < MAXFIX) g_fixlist[slot] = (int)(eidx + 1);
        }
        const int j2 = i - 4;
        if (j2 >= 0) {
            float4 v = ring[j2 % 9];
            s.x -= v.x; s.y -= v.y; s.z -= v.z; s.w -= v.w;
        }
    }
}

// ---------------------------------------------------------------------------
// Stage 3: exact fixup — reference's sequential in-bounds 729-tap fold
// (ascending z,h,w; fp32 adds; init 0) over the bit-exact g_p field.
// ---------------------------------------------------------------------------
__global__ __launch_bounds__(256) void fixup_kernel(float* __restrict__ out)
{
    int cnt = g_cnt; if (cnt > MAXFIX) cnt = MAXFIX;
    for (int idx = blockIdx.x*256 + threadIdx.x; idx < cnt; idx += gridDim.x*256) {
        const int v    = g_fixlist[idx];
        const int chan = v >> 18;
        const int rem  = v & (NVOX-1);
        const int z = rem >> 12;
        const int h = (rem >> 6) & 63;
        const int w = rem & 63;
        const long cb = (long)chan*NVOX;

        const int zlo = z-4 < 0 ? 0 : z-4, zhi = z+4 > 63 ? 63 : z+4;
        const int hlo = h-4 < 0 ? 0 : h-4, hhi = h+4 > 63 ? 63 : h+4;
        const int wlo = w-4 < 0 ? 0 : w-4, whi = w+4 > 63 ? 63 : w+4;

        float sD = 0.f, sN = 0.f;
        for (int dz = zlo; dz <= zhi; dz++)
            for (int dh = hlo; dh <= hhi; dh++) {
                const float2* row = g_p + cb + ((long)dz*D + dh)*D;
                for (int dw = wlo; dw <= whi; dw++) {
                    float2 x = row[dw];
                    sD = __fadd_rn(sD, x.x);
                    sN = __fadd_rn(sN, x.y);
                }
            }
        out[v] = __fdiv_rn(sN, sD);
    }
}

extern "C" void kernel_launch(void* const* d_in, const int* in_sizes, int n_in,
                              void* d_out, int out_size) {
    (void)in_sizes; (void)n_in; (void)out_size;
    const float* mov = (const float*)d_in[0];
    const float* fix = (const float*)d_in[1];
    const float* qw  = (const float*)d_in[2];
    const float* kw  = (const float*)d_in[3];
    const float* vw  = (const float*)d_in[4];
    float* out = (float*)d_out;

    const int wh_smem = 2*D*PSTR * sizeof(float2);      // 66560 B
    cudaFuncSetAttribute(box_wh_kernel,
                         cudaFuncAttributeMaxDynamicSharedMemorySize, wh_smem);

    reset_kernel<<<1, 1>>>();
    proj_kernel<<<(NB*NVOX)/256, 256>>>(mov, fix, qw, kw, vw);
    box_wh_kernel<<<dim3(D, NCH), 256, wh_smem>>>();
    box_z_div_kernel<<<dim3(8, NCH), 256>>>(out);
    fixup_kernel<<<512, 256>>>(out);
}

// round 8
// speedup vs baseline: 1.5092x; 1.3584x over previous
#include <cuda_runtime.h>

#define NB 2
#define NC 64
#define D  64
#define NVOX (D*D*D)            // 262144
#define NCH  (NB*NC)            // 128
#define TOT  (NCH*NVOX)         // 33554432

#define FIX_T   0.02f
#define MAXFIX  (1<<22)

#define PSTR 65                 // padded smem row stride (float2 elems)

// Scratch (no cudaMalloc allowed)
__device__ float2 g_p [TOT];    // (qk, qkv) bit-exact proj output (fixup source)
__device__ float2 g_t2[TOT];    // after w+h passes
__device__ int    g_cnt;
__device__ int    g_fixlist[MAXFIX];

__global__ void reset_kernel() { g_cnt = 0; }
__global__ void noop_kernel() {}

// ---------------------------------------------------------------------------
// Stage 1: per-voxel projections (R4-proven math, 128-thread blocks).
// aq/ak as one packed fma.rn.f32x2 chain (each lane IEEE fp32 -> bit-identical
// to scalar sequential ascending-c chains); av as scalar FFMA chain.
// qk = q*k; qkv = qk*v single roundings. Bit-exactness of g_p is load-bearing
// for near-zero-denominator voxels (see fixup). 128 threads @ <=255 regs ->
// 2 blocks/SM (16 warps) with zero spill.
// ---------------------------------------------------------------------------
__global__ __launch_bounds__(128) void proj_kernel(
    const float* __restrict__ mov, const float* __restrict__ fix,
    const float* __restrict__ qw,  const float* __restrict__ kw,
    const float* __restrict__ vw)
{
    __shared__ float2 swqk[NC*NC];   // (wq, wk) interleaved, 32 KB
    __shared__ float  swv [NC*NC];   // 16 KB
    const int tid = threadIdx.x;
    for (int i = tid; i < NC*NC; i += 128) {
        swqk[i] = make_float2(qw[i], kw[i]);
        swv[i]  = vw[i];
    }
    __syncthreads();

    const int gid = blockIdx.x * 128 + tid;     // 0 .. NB*NVOX-1
    const int b   = (gid >= NVOX) ? 1 : 0;
    const int n   = gid - b * NVOX;

    const float* mp = mov + (long)b*NC*NVOX + n;
    const float* fp = fix + (long)b*NC*NVOX + n;

    unsigned long long mf[NC];   // packed (m[c], f[c])
    float f[NC];
    #pragma unroll
    for (int c = 0; c < NC; c++) {
        const float mv = mp[(long)c*NVOX];
        const float fv = fp[(long)c*NVOX];
        f[c] = fv;
        asm("mov.b64 %0, {%1,%2};" : "=l"(mf[c]) : "f"(mv), "f"(fv));
    }

    float2* op = g_p + (long)b*NC*NVOX + n;

    for (int l = 0; l < NC; l++) {
        const ulonglong2* wrow = (const ulonglong2*)(swqk + (l<<6));
        const float4*     vrow = (const float4*)(swv + (l<<6));
        unsigned long long aqk = 0ull;   // lanes: (aq, ak)
        float av = 0.f;
        #pragma unroll
        for (int j = 0; j < NC/4; j++) {
            const ulonglong2 wa = wrow[2*j];      // c = 4j, 4j+1
            const ulonglong2 wb = wrow[2*j+1];    // c = 4j+2, 4j+3
            const float4 wv4 = vrow[j];
            asm("fma.rn.f32x2 %0, %1, %2, %0;" : "+l"(aqk) : "l"(wa.x), "l"(mf[4*j+0]));
            av = __fmaf_rn(wv4.x, f[4*j+0], av);
            asm("fma.rn.f32x2 %0, %1, %2, %0;" : "+l"(aqk) : "l"(wa.y), "l"(mf[4*j+1]));
            av = __fmaf_rn(wv4.y, f[4*j+1], av);
            asm("fma.rn.f32x2 %0, %1, %2, %0;" : "+l"(aqk) : "l"(wb.x), "l"(mf[4*j+2]));
            av = __fmaf_rn(wv4.z, f[4*j+2], av);
            asm("fma.rn.f32x2 %0, %1, %2, %0;" : "+l"(aqk) : "l"(wb.y), "l"(mf[4*j+3]));
            av = __fmaf_rn(wv4.w, f[4*j+3], av);
        }
        float aq, ak;
        asm("mov.b64 {%0,%1}, %2;" : "=f"(aq), "=f"(ak) : "l"(aqk));
        const float qk  = __fmul_rn(aq, ak);
        const float qkv = __fmul_rn(qk, av);
        op[(long)l*NVOX] = make_float2(qk, qkv);
    }
}

// ---------------------------------------------------------------------------
// Stage 2ab (fused): box sums along W then H for one (chan, z) plane.
// Sliding windows re-read the add/subtract taps from smem directly —
// NO local-memory ring arrays (the R6/R7 box_wh failure mode).
// Arithmetic sequence identical to the validated ring version.
// ---------------------------------------------------------------------------
__global__ __launch_bounds__(256) void box_wh_kernel()
{
    extern __shared__ float2 smp[];
    float2* P = smp;               // [64][PSTR] input plane
    float2* Q = smp + D*PSTR;      // [64][PSTR] after w-pass

    const int tid  = threadIdx.x;
    const int z    = blockIdx.x;
    const int chan = blockIdx.y;
    const long base = (long)chan*NVOX + (long)z*(D*D);

    // load plane (coalesced float2)
    for (int i = tid; i < D*D; i += 256) {
        P[(i >> 6)*PSTR + (i & 63)] = g_p[base + i];
    }
    __syncthreads();

    // w-pass: thread = (h = tid&63, seg = tid>>6), 16 outputs per thread
    {
        const int h   = tid & 63;
        const int w0  = (tid >> 6) * 16;
        const float2* row = P + h*PSTR;
        float2* qrow = Q + h*PSTR;
        float sx = 0.f, sy = 0.f;
        const int j0 = (w0 >= 4) ? (w0 - 4) : 0;
        for (int j = j0; j < w0 + 4; j++) { sx += row[j].x; sy += row[j].y; }
        #pragma unroll
        for (int i = 0; i < 16; i++) {
            const int w = w0 + i;
            if (w + 4 < D) { sx += row[w+4].x; sy += row[w+4].y; }
            qrow[w] = make_float2(sx, sy);
            if (w >= 4) { sx -= row[w-4].x; sy -= row[w-4].y; }
        }
    }
    __syncthreads();

    // h-pass: thread = (w = tid&63, seg = tid>>6), write g_t2
    {
        const int w   = tid & 63;
        const int h0  = (tid >> 6) * 16;
        float sx = 0.f, sy = 0.f;
        const int j0 = (h0 >= 4) ? (h0 - 4) : 0;
        for (int j = j0; j < h0 + 4; j++) {
            const float2 v = Q[j*PSTR + w];
            sx += v.x; sy += v.y;
        }
        #pragma unroll
        for (int i = 0; i < 16; i++) {
            const int h = h0 + i;
            if (h + 4 < D) {
                const float2 v = Q[(h+4)*PSTR + w];
                sx += v.x; sy += v.y;
            }
            g_t2[base + h*D + w] = make_float2(sx, sy);
            if (h >= 4) {
                const float2 v = Q[(h-4)*PSTR + w];
                sx -= v.x; sy -= v.y;
            }
        }
    }
}

// ---------------------------------------------------------------------------
// Stage 2c: box sum along Z + division; flag near-zero denominators.
// g_t2 -> out   (compile-time-indexed ring -> registers; measured 108 us)
// ---------------------------------------------------------------------------
__global__ __launch_bounds__(256) void box_z_div_kernel(float* __restrict__ out)
{
    const int t    = threadIdx.x;
    const int wp   = t & 31;
    const int h    = blockIdx.x * 8 + (t >> 5);   // gridDim.x = 8
    const int chan = blockIdx.y;
    const long ebase = (long)chan*NVOX + (long)h*D + 2*wp;
    const long base  = ebase >> 1;
    const float4* src = (const float4*)g_t2;
    float2*       o2  = (float2*)out;

    float4 ring[9];
    float4 s = make_float4(0.f, 0.f, 0.f, 0.f);
    #pragma unroll
    for (int j = 0; j < 4; j++) {
        float4 v = src[base + (long)j*(D*D/2)];
        ring[j % 9] = v;
        s.x += v.x; s.y += v.y; s.z += v.z; s.w += v.w;
    }
    #pragma unroll
    for (int i = 0; i < D; i++) {
        const int j = i + 4;
        if (j < D) {
            float4 v = src[base + (long)j*(D*D/2)];
            ring[j % 9] = v;
            s.x += v.x; s.y += v.y; s.z += v.z; s.w += v.w;
        }
        const long eidx = ebase + (long)i*(D*D);
        o2[eidx >> 1] = make_float2(__fdiv_rn(s.y, s.x), __fdiv_rn(s.w, s.z));
        if (fabsf(s.x) < FIX_T) {
            int slot = atomicAdd(&g_cnt, 1);
            if (slot < MAXFIX) g_fixlist[slot] = (int)eidx;
        }
        if (fabsf(s.z) < FIX_T) {
            int slot = atomicAdd(&g_cnt, 1);
            if (slot < MAXFIX) g_fixlist[slot] = (int)(eidx + 1);
        }
        const int j2 = i - 4;
        if (j2 >= 0) {
            float4 v = ring[j2 % 9];
            s.x -= v.x; s.y -= v.y; s.z -= v.z; s.w -= v.w;
        }
    }
}

// ---------------------------------------------------------------------------
// Stage 3: exact fixup — reference's sequential in-bounds 729-tap fold
// (ascending z,h,w; fp32 adds; init 0) over the bit-exact g_p field.
// ---------------------------------------------------------------------------
__global__ __launch_bounds__(256) void fixup_kernel(float* __restrict__ out)
{
    int cnt = g_cnt; if (cnt > MAXFIX) cnt = MAXFIX;
    for (int idx = blockIdx.x*256 + threadIdx.x; idx < cnt; idx += gridDim.x*256) {
        const int v    = g_fixlist[idx];
        const int chan = v >> 18;
        const int rem  = v & (NVOX-1);
        const int z = rem >> 12;
        const int h = (rem >> 6) & 63;
        const int w = rem & 63;
        const long cb = (long)chan*NVOX;

        const int zlo = z-4 < 0 ? 0 : z-4, zhi = z+4 > 63 ? 63 : z+4;
        const int hlo = h-4 < 0 ? 0 : h-4, hhi = h+4 > 63 ? 63 : h+4;
        const int wlo = w-4 < 0 ? 0 : w-4, whi = w+4 > 63 ? 63 : w+4;

        float sD = 0.f, sN = 0.f;
        for (int dz = zlo; dz <= zhi; dz++)
            for (int dh = hlo; dh <= hhi; dh++) {
                const float2* row = g_p + cb + ((long)dz*D + dh)*D;
                for (int dw = wlo; dw <= whi; dw++) {
                    float2 x = row[dw];
                    sD = __fadd_rn(sD, x.x);
                    sN = __fadd_rn(sN, x.y);
                }
            }
        out[v] = __fdiv_rn(sN, sD);
    }
}

extern "C" void kernel_launch(void* const* d_in, const int* in_sizes, int n_in,
                              void* d_out, int out_size) {
    (void)in_sizes; (void)n_in; (void)out_size;
    const float* mov = (const float*)d_in[0];
    const float* fix = (const float*)d_in[1];
    const float* qw  = (const float*)d_in[2];
    const float* kw  = (const float*)d_in[3];
    const float* vw  = (const float*)d_in[4];
    float* out = (float*)d_out;

    const int wh_smem = 2*D*PSTR * sizeof(float2);      // 66560 B
    cudaFuncSetAttribute(box_wh_kernel,
                         cudaFuncAttributeMaxDynamicSharedMemorySize, wh_smem);

    reset_kernel<<<1, 1>>>();
    noop_kernel<<<1, 32>>>();
    noop_kernel<<<1, 32>>>();          // proj lands at captured launch index 3
    proj_kernel<<<(NB*NVOX)/128, 128>>>(mov, fix, qw, kw, vw);
    box_wh_kernel<<<dim3(D, NCH), 256, wh_smem>>>();
    box_z_div_kernel<<<dim3(8, NCH), 256>>>(out);
    fixup_kernel<<<512, 256>>>(out);
}

// round 9
// speedup vs baseline: 1.6083x; 1.0656x over previous
#include <cuda_runtime.h>

#define NB 2
#define NC 64
#define D  64
#define NVOX (D*D*D)            // 262144
#define NCH  (NB*NC)            // 128
#define TOT  (NCH*NVOX)         // 33554432

#define FIX_T   0.02f
#define MAXFIX  (1<<22)

#define PSTR 65                 // padded smem row stride (float2 elems)
#define ZPB  8                  // z-planes per box_wh block

// Scratch (no cudaMalloc allowed)
__device__ float2 g_p [TOT];    // (qk, qkv) bit-exact proj output (fixup source)
__device__ float2 g_t2[TOT];    // after w+h passes
__device__ int    g_cnt;
__device__ int    g_fixlist[MAXFIX];

__global__ void reset_kernel() { g_cnt = 0; }
__global__ void noop_kernel() {}

// ---------------------------------------------------------------------------
// Stage 1: per-voxel projections (unchanged from R8's measured 387us version).
// aq/ak as one packed fma.rn.f32x2 chain (each lane IEEE fp32 -> bit-identical
// to scalar sequential ascending-c chains); av as scalar FFMA chain.
// Bit-exactness of g_p is load-bearing for near-zero denominators (fixup).
// ---------------------------------------------------------------------------
__global__ __launch_bounds__(128) void proj_kernel(
    const float* __restrict__ mov, const float* __restrict__ fix,
    const float* __restrict__ qw,  const float* __restrict__ kw,
    const float* __restrict__ vw)
{
    __shared__ float2 swqk[NC*NC];   // (wq, wk) interleaved, 32 KB
    __shared__ float  swv [NC*NC];   // 16 KB
    const int tid = threadIdx.x;
    for (int i = tid; i < NC*NC; i += 128) {
        swqk[i] = make_float2(qw[i], kw[i]);
        swv[i]  = vw[i];
    }
    __syncthreads();

    const int gid = blockIdx.x * 128 + tid;     // 0 .. NB*NVOX-1
    const int b   = (gid >= NVOX) ? 1 : 0;
    const int n   = gid - b * NVOX;

    const float* mp = mov + (long)b*NC*NVOX + n;
    const float* fp = fix + (long)b*NC*NVOX + n;

    unsigned long long mf[NC];   // packed (m[c], f[c])
    float f[NC];
    #pragma unroll
    for (int c = 0; c < NC; c++) {
        const float mv = mp[(long)c*NVOX];
        const float fv = fp[(long)c*NVOX];
        f[c] = fv;
        asm("mov.b64 %0, {%1,%2};" : "=l"(mf[c]) : "f"(mv), "f"(fv));
    }

    float2* op = g_p + (long)b*NC*NVOX + n;

    for (int l = 0; l < NC; l++) {
        const ulonglong2* wrow = (const ulonglong2*)(swqk + (l<<6));
        const float4*     vrow = (const float4*)(swv + (l<<6));
        unsigned long long aqk = 0ull;   // lanes: (aq, ak)
        float av = 0.f;
        #pragma unroll
        for (int j = 0; j < NC/4; j++) {
            const ulonglong2 wa = wrow[2*j];
            const ulonglong2 wb = wrow[2*j+1];
            const float4 wv4 = vrow[j];
            asm("fma.rn.f32x2 %0, %1, %2, %0;" : "+l"(aqk) : "l"(wa.x), "l"(mf[4*j+0]));
            av = __fmaf_rn(wv4.x, f[4*j+0], av);
            asm("fma.rn.f32x2 %0, %1, %2, %0;" : "+l"(aqk) : "l"(wa.y), "l"(mf[4*j+1]));
            av = __fmaf_rn(wv4.y, f[4*j+1], av);
            asm("fma.rn.f32x2 %0, %1, %2, %0;" : "+l"(aqk) : "l"(wb.x), "l"(mf[4*j+2]));
            av = __fmaf_rn(wv4.z, f[4*j+2], av);
            asm("fma.rn.f32x2 %0, %1, %2, %0;" : "+l"(aqk) : "l"(wb.y), "l"(mf[4*j+3]));
            av = __fmaf_rn(wv4.w, f[4*j+3], av);
        }
        float aq, ak;
        asm("mov.b64 {%0,%1}, %2;" : "=f"(aq), "=f"(ak) : "l"(aqk));
        const float qk  = __fmul_rn(aq, ak);
        const float qkv = __fmul_rn(qk, av);
        op[(long)l*NVOX] = make_float2(qk, qkv);
    }
}

// ---------------------------------------------------------------------------
// Stage 2ab (fused, software-pipelined): W then H box sums.
// Block = 8 consecutive z-planes of one channel. Plane p+1 is prefetched into
// registers (two 8xfloat2 batches, compile-time indices) WHILE plane p's
// w/h passes run, then committed to smem P after the barrier. Per-plane pass
// arithmetic identical to the validated R8 version.
// ---------------------------------------------------------------------------
__global__ __launch_bounds__(256) void box_wh_kernel()
{
    extern __shared__ float2 smp[];
    float2* P = smp;               // [64][PSTR] current input plane
    float2* Q = smp + D*PSTR;      // [64][PSTR] after w-pass

    const int tid  = threadIdx.x;
    const int z0   = blockIdx.x * ZPB;
    const int chan = blockIdx.y;
    const long cb  = (long)chan*NVOX;

    // initial plane load (coalesced float2)
    for (int i = tid; i < D*D; i += 256)
        P[(i >> 6)*PSTR + (i & 63)] = g_p[cb + (long)z0*(D*D) + i];
    __syncthreads();

    #pragma unroll 1
    for (int p = 0; p < ZPB; p++) {
        const long nb = cb + (long)(z0 + p + 1)*(D*D);   // next plane base
        const bool pf = (p + 1 < ZPB);
        float2 rA[8], rB[8];

        // prefetch batch A (overlaps w-pass)
        if (pf) {
            #pragma unroll
            for (int k = 0; k < 8; k++) rA[k] = g_p[nb + k*256 + tid];
        }

        // w-pass: P -> Q (identical arithmetic to R8)
        {
            const int h   = tid & 63;
            const int w0  = (tid >> 6) * 16;
            const float2* row = P + h*PSTR;
            float2* qrow = Q + h*PSTR;
            float sx = 0.f, sy = 0.f;
            const int j0 = (w0 >= 4) ? (w0 - 4) : 0;
            for (int j = j0; j < w0 + 4; j++) { sx += row[j].x; sy += row[j].y; }
            #pragma unroll
            for (int i = 0; i < 16; i++) {
                const int w = w0 + i;
                if (w + 4 < D) { sx += row[w+4].x; sy += row[w+4].y; }
                qrow[w] = make_float2(sx, sy);
                if (w >= 4) { sx -= row[w-4].x; sy -= row[w-4].y; }
            }
        }
        __syncthreads();   // Q complete; all w-pass reads of P done

        // prefetch batch B (overlaps h-pass)
        if (pf) {
            #pragma unroll
            for (int k = 0; k < 8; k++) rB[k] = g_p[nb + (k+8)*256 + tid];
        }

        // h-pass: Q -> g_t2 (identical arithmetic to R8)
        {
            const int w   = tid & 63;
            const int h0  = (tid >> 6) * 16;
            const long pbase = cb + (long)(z0 + p)*(D*D);
            float sx = 0.f, sy = 0.f;
            const int j0 = (h0 >= 4) ? (h0 - 4) : 0;
            for (int j = j0; j < h0 + 4; j++) {
                const float2 v = Q[j*PSTR + w];
                sx += v.x; sy += v.y;
            }
            #pragma unroll
            for (int i = 0; i < 16; i++) {
                const int h = h0 + i;
                if (h + 4 < D) {
                    const float2 v = Q[(h+4)*PSTR + w];
                    sx += v.x; sy += v.y;
                }
                g_t2[pbase + h*D + w] = make_float2(sx, sy);
                if (h >= 4) {
                    const float2 v = Q[(h-4)*PSTR + w];
                    sx -= v.x; sy -= v.y;
                }
            }
        }

        // commit prefetched plane into P (P free since sync above)
        if (pf) {
            #pragma unroll
            for (int k = 0; k < 8; k++) {
                const int i = k*256 + tid;
                P[(i >> 6)*PSTR + (i & 63)] = rA[k];
            }
            #pragma unroll
            for (int k = 0; k < 8; k++) {
                const int i = (k+8)*256 + tid;
                P[(i >> 6)*PSTR + (i & 63)] = rB[k];
            }
        }
        __syncthreads();   // P_next ready; Q reads complete
    }
}

// ---------------------------------------------------------------------------
// Stage 2c: box sum along Z + division; flag near-zero denominators.
// g_t2 -> out  (measured 108us, DRAM-bound)
// ---------------------------------------------------------------------------
__global__ __launch_bounds__(256) void box_z_div_kernel(float* __restrict__ out)
{
    const int t    = threadIdx.x;
    const int wp   = t & 31;
    const int h    = blockIdx.x * 8 + (t >> 5);   // gridDim.x = 8
    const int chan = blockIdx.y;
    const long ebase = (long)chan*NVOX + (long)h*D + 2*wp;
    const long base  = ebase >> 1;
    const float4* src = (const float4*)g_t2;
    float2*       o2  = (float2*)out;

    float4 ring[9];
    float4 s = make_float4(0.f, 0.f, 0.f, 0.f);
    #pragma unroll
    for (int j = 0; j < 4; j++) {
        float4 v = src[base + (long)j*(D*D/2)];
        ring[j % 9] = v;
        s.x += v.x; s.y += v.y; s.z += v.z; s.w += v.w;
    }
    #pragma unroll
    for (int i = 0; i < D; i++) {
        const int j = i + 4;
        if (j < D) {
            float4 v = src[base + (long)j*(D*D/2)];
            ring[j % 9] = v;
            s.x += v.x; s.y += v.y; s.z += v.z; s.w += v.w;
        }
        const long eidx = ebase + (long)i*(D*D);
        o2[eidx >> 1] = make_float2(__fdiv_rn(s.y, s.x), __fdiv_rn(s.w, s.z));
        if (fabsf(s.x) < FIX_T) {
            int slot = atomicAdd(&g_cnt, 1);
            if (slot < MAXFIX) g_fixlist[slot] = (int)eidx;
        }
        if (fabsf(s.z) < FIX_T) {
            int slot = atomicAdd(&g_cnt, 1);
            if (slot < MAXFIX) g_fixlist[slot] = (int)(eidx + 1);
        }
        const int j2 = i - 4;
        if (j2 >= 0) {
            float4 v = ring[j2 % 9];
            s.x -= v.x; s.y -= v.y; s.z -= v.z; s.w -= v.w;
        }
    }
}

// ---------------------------------------------------------------------------
// Stage 3: exact fixup — reference's sequential in-bounds 729-tap fold
// (ascending z,h,w; fp32 adds; init 0) over the bit-exact g_p field.
// ---------------------------------------------------------------------------
__global__ __launch_bounds__(256) void fixup_kernel(float* __restrict__ out)
{
    int cnt = g_cnt; if (cnt > MAXFIX) cnt = MAXFIX;
    for (int idx = blockIdx.x*256 + threadIdx.x; idx < cnt; idx += gridDim.x*256) {
        const int v    = g_fixlist[idx];
        const int chan = v >> 18;
        const int rem  = v & (NVOX-1);
        const int z = rem >> 12;
        const int h = (rem >> 6) & 63;
        const int w = rem & 63;
        const long cb = (long)chan*NVOX;

        const int zlo = z-4 < 0 ? 0 : z-4, zhi = z+4 > 63 ? 63 : z+4;
        const int hlo = h-4 < 0 ? 0 : h-4, hhi = h+4 > 63 ? 63 : h+4;
        const int wlo = w-4 < 0 ? 0 : w-4, whi = w+4 > 63 ? 63 : w+4;

        float sD = 0.f, sN = 0.f;
        for (int dz = zlo; dz <= zhi; dz++)
            for (int dh = hlo; dh <= hhi; dh++) {
                const float2* row = g_p + cb + ((long)dz*D + dh)*D;
                for (int dw = wlo; dw <= whi; dw++) {
                    float2 x = row[dw];
                    sD = __fadd_rn(sD, x.x);
                    sN = __fadd_rn(sN, x.y);
                }
            }
        out[v] = __fdiv_rn(sN, sD);
    }
}

extern "C" void kernel_launch(void* const* d_in, const int* in_sizes, int n_in,
                              void* d_out, int out_size) {
    (void)in_sizes; (void)n_in; (void)out_size;
    const float* mov = (const float*)d_in[0];
    const float* fix = (const float*)d_in[1];
    const float* qw  = (const float*)d_in[2];
    const float* kw  = (const float*)d_in[3];
    const float* vw  = (const float*)d_in[4];
    float* out = (float*)d_out;

    const int wh_smem = 2*D*PSTR * sizeof(float2);      // 66560 B
    cudaFuncSetAttribute(box_wh_kernel,
                         cudaFuncAttributeMaxDynamicSharedMemorySize, wh_smem);

    reset_kernel<<<1, 1>>>();
    noop_kernel<<<1, 32>>>();
    proj_kernel<<<(NB*NVOX)/128, 128>>>(mov, fix, qw, kw, vw);
    box_wh_kernel<<<dim3(D/ZPB, NCH), 256, wh_smem>>>();   // captured idx 3
    box_z_div_kernel<<<dim3(8, NCH), 256>>>(out);
    fixup_kernel<<<512, 256>>>(out);
}